// round 1
// baseline (speedup 1.0000x reference)
#include <cuda_runtime.h>

typedef unsigned long long u64;

#define NB 256
#define NLAYER 19

__device__ __forceinline__ u64 pk2(float a, float b) {
    u64 r; asm("mov.b64 %0,{%1,%2};" : "=l"(r) : "f"(a), "f"(b)); return r;
}
__device__ __forceinline__ void unpk2(u64 v, float& a, float& b) {
    asm("mov.b64 {%0,%1},%2;" : "=f"(a), "=f"(b) : "l"(v));
}
__device__ __forceinline__ u64 ffma2(u64 a, u64 b, u64 c) {
    u64 d; asm("fma.rn.f32x2 %0,%1,%2,%3;" : "=l"(d) : "l"(a), "l"(b), "l"(c)); return d;
}
__device__ __forceinline__ u64 fmul2(u64 a, u64 b) {
    u64 d; asm("mul.rn.f32x2 %0,%1,%2;" : "=l"(d) : "l"(a), "l"(b)); return d;
}
__device__ __forceinline__ float ex2f(float x) {
    float r; asm("ex2.approx.f32 %0,%1;" : "=f"(r) : "f"(x)); return r;
}

// ELU on a packed f32x2 value: x>0 ? x : exp(x)-1
__device__ __forceinline__ u64 elu2(u64 v, u64 kL2E) {
    float a, b; unpk2(v, a, b);
    u64 t = fmul2(v, kL2E);          // x * log2(e), packed
    float ta, tb; unpk2(t, ta, tb);
    float ea = ex2f(ta) - 1.0f;      // exp(x)-1 (approx fine: abs err ~2e-7)
    float eb = ex2f(tb) - 1.0f;
    a = (a > 0.0f) ? a : ea;
    b = (b > 0.0f) ? b : eb;
    return pk2(a, b);
}

// exact-ish 2-class log_softmax per scalar element
__device__ __forceinline__ void lsm2(float z0, float z1, float& o0, float& o1) {
    float m  = fmaxf(z0, z1);
    float d  = fminf(z0, z1) - m;          // <= 0
    float t  = log1pf(__expf(d));          // log(1 + e^d), accurate for small e^d
    bool  w  = (z0 >= z1);
    o0 = w ? -t : (d - t);
    o1 = w ? (d - t) : -t;
}

__global__ __launch_bounds__(NB) void mlp_kernel(
    const float* __restrict__ x,
    const float* __restrict__ W1,  const float* __restrict__ b1,
    const float* __restrict__ Wm,  const float* __restrict__ bm,
    const float* __restrict__ W21, const float* __restrict__ b21,
    float* __restrict__ out)
{
    // weights staged to shared, pre-duplicated (w,w) so LDS.64 feeds both f32x2 halves
    __shared__ u64 sW1[18], sb1[9], sW[NLAYER * 81], sb[NLAYER * 9], sW21[18], sb21[2];

    int tid = threadIdx.x;
    for (int i = tid; i < 18;          i += NB) sW1[i]  = pk2(W1[i],  W1[i]);
    for (int i = tid; i < 9;           i += NB) sb1[i]  = pk2(b1[i],  b1[i]);
    for (int i = tid; i < NLAYER * 81; i += NB) sW[i]   = pk2(Wm[i],  Wm[i]);
    for (int i = tid; i < NLAYER * 9;  i += NB) sb[i]   = pk2(bm[i],  bm[i]);
    for (int i = tid; i < 18;          i += NB) sW21[i] = pk2(W21[i], W21[i]);
    for (int i = tid; i < 2;           i += NB) sb21[i] = pk2(b21[i], b21[i]);
    __syncthreads();

    const u64 kL2E = pk2(1.4426950408889634f, 1.4426950408889634f);

    unsigned p = blockIdx.x * NB + tid;          // pair index: elements 2p, 2p+1
    float4 X = reinterpret_cast<const float4*>(x)[p];  // coalesced 16B load
    u64 x0 = pk2(X.x, X.z);   // feature 0 of both elements
    u64 x1 = pk2(X.y, X.w);   // feature 1 of both elements

    // fc1: 9x2 + ELU
    u64 h[9];
#pragma unroll
    for (int j = 0; j < 9; j++) {
        u64 acc = sb1[j];
        acc = ffma2(sW1[j * 2 + 0], x0, acc);
        acc = ffma2(sW1[j * 2 + 1], x1, acc);
        h[j] = elu2(acc, kL2E);
    }

    // fc2..fc20: 19 layers of 9x9 + ELU (looped for I$ locality, inner fully unrolled)
#pragma unroll 1
    for (int l = 0; l < NLAYER; l++) {
        const u64* W = &sW[l * 81];
        const u64* bb = &sb[l * 9];
        u64 nh[9];
#pragma unroll
        for (int j = 0; j < 9; j++) {
            u64 acc = bb[j];
#pragma unroll
            for (int i = 0; i < 9; i++)
                acc = ffma2(W[j * 9 + i], h[i], acc);
            nh[j] = acc;
        }
#pragma unroll
        for (int j = 0; j < 9; j++)
            h[j] = elu2(nh[j], kL2E);
    }

    // fc21: 2x9 (no activation)
    u64 L0 = sb21[0], L1 = sb21[1];
#pragma unroll
    for (int i = 0; i < 9; i++) {
        L0 = ffma2(sW21[i],     h[i], L0);
        L1 = ffma2(sW21[9 + i], h[i], L1);
    }

    float z0a, z0b, z1a, z1b;
    unpk2(L0, z0a, z0b);
    unpk2(L1, z1a, z1b);

    float o0a, o1a, o0b, o1b;
    lsm2(z0a, z1a, o0a, o1a);
    lsm2(z0b, z1b, o0b, o1b);

    reinterpret_cast<float4*>(out)[p] = make_float4(o0a, o1a, o0b, o1b);
}

extern "C" void kernel_launch(void* const* d_in, const int* in_sizes, int n_in,
                              void* d_out, int out_size)
{
    const float* x   = (const float*)d_in[0];
    const float* W1  = (const float*)d_in[1];
    const float* b1  = (const float*)d_in[2];
    const float* Wm  = (const float*)d_in[3];
    const float* bm  = (const float*)d_in[4];
    const float* W21 = (const float*)d_in[5];
    const float* b21 = (const float*)d_in[6];
    float* out = (float*)d_out;

    int n_elems = in_sizes[0] / 2;   // B
    int n_pairs = n_elems / 2;
    int grid = (n_pairs + NB - 1) / NB;

    mlp_kernel<<<grid, NB>>>(x, W1, b1, Wm, bm, W21, b21, out);
}

// round 3
// speedup vs baseline: 1.1353x; 1.1353x over previous
#include <cuda_runtime.h>

typedef unsigned long long u64;

#define NB 256
#define NLAYER 19

__device__ __forceinline__ u64 pk2(float a, float b) {
    u64 r; asm("mov.b64 %0,{%1,%2};" : "=l"(r) : "f"(a), "f"(b)); return r;
}
__device__ __forceinline__ void unpk2(u64 v, float& a, float& b) {
    asm("mov.b64 {%0,%1},%2;" : "=f"(a), "=f"(b) : "l"(v));
}
__device__ __forceinline__ u64 ffma2(u64 a, u64 b, u64 c) {
    u64 d; asm("fma.rn.f32x2 %0,%1,%2,%3;" : "=l"(d) : "l"(a), "l"(b), "l"(c)); return d;
}
__device__ __forceinline__ u64 fmul2(u64 a, u64 b) {
    u64 d; asm("mul.rn.f32x2 %0,%1,%2;" : "=l"(d) : "l"(a), "l"(b)); return d;
}
__device__ __forceinline__ u64 fadd2(u64 a, u64 b) {
    u64 d; asm("add.rn.f32x2 %0,%1,%2;" : "=l"(d) : "l"(a), "l"(b)); return d;
}
__device__ __forceinline__ float ex2f(float x) {
    float r; asm("ex2.approx.f32 %0,%1;" : "=f"(r) : "f"(x)); return r;
}

#define L2E 1.4426950408889634f

// "shifted ELU": g(x) = elu(x) + 1 = max(x,0) + min(exp(x),1)
// The -1 is folded into the NEXT layer's (pre-adjusted) bias.
// No predicates; FMNMX goes to the alu pipe; overflow-safe (min(inf,1)=1).
__device__ __forceinline__ u64 act2(u64 v, u64 kL2E) {
    float a, b; unpk2(v, a, b);
    u64 t = fmul2(v, kL2E);
    float ta, tb; unpk2(t, ta, tb);
    float ea = ex2f(ta), eb = ex2f(tb);
    float ma = fmaxf(a, 0.0f), mb = fmaxf(b, 0.0f);
    float na = fminf(ea, 1.0f), nb = fminf(eb, 1.0f);
    return fadd2(pk2(ma, mb), pk2(na, nb));
}

// exact-ish 2-class log_softmax per scalar element
__device__ __forceinline__ void lsm2(float z0, float z1, float& o0, float& o1) {
    float m  = fmaxf(z0, z1);
    float d  = fminf(z0, z1) - m;          // <= 0
    float t  = log1pf(__expf(d));
    bool  w  = (z0 >= z1);
    o0 = w ? -t : (d - t);
    o1 = w ? (d - t) : -t;
}

__global__ __launch_bounds__(NB, 2) void mlp_kernel(
    const float* __restrict__ x,
    const float* __restrict__ W1,  const float* __restrict__ b1,
    const float* __restrict__ Wm,  const float* __restrict__ bm,
    const float* __restrict__ W21, const float* __restrict__ b21,
    float* __restrict__ out)
{
    // weights duplicated (w,w) as u64 so one LDS feeds an f32x2 FFMA.
    // middle-layer rows padded to 10 u64 so 16B LDS.128 pair loads stay aligned.
    __shared__ __align__(16) u64 sW[NLAYER * 90];
    __shared__ u64 sW1[18], sb1[9], sb[NLAYER * 9], sW21[18], sb21[2];

    int tid = threadIdx.x;
    for (int i = tid; i < 18; i += NB) sW1[i]  = pk2(W1[i],  W1[i]);
    for (int i = tid; i < 9;  i += NB) sb1[i]  = pk2(b1[i],  b1[i]);   // fc1 bias NOT adjusted (consumes raw x)
    for (int idx = tid; idx < NLAYER * 81; idx += NB) {
        int l = idx / 81, r = idx % 81, j = r / 9, i = r % 9;
        float w = Wm[idx];
        sW[l * 90 + j * 10 + i] = pk2(w, w);
    }
    // adjusted biases: b' = b - sum_i W_ji  (absorbs the "+1" shift of incoming activations)
    for (int idx = tid; idx < NLAYER * 9; idx += NB) {
        int l = idx / 9, j = idx % 9;
        float s = bm[idx];
#pragma unroll
        for (int i = 0; i < 9; i++) s -= Wm[l * 81 + j * 9 + i];
        sb[idx] = pk2(s, s);
    }
    for (int i = tid; i < 18; i += NB) sW21[i] = pk2(W21[i], W21[i]);
    if (tid < 2) {
        float s = b21[tid];
#pragma unroll
        for (int i = 0; i < 9; i++) s -= W21[tid * 9 + i];
        sb21[tid] = pk2(s, s);
    }
    __syncthreads();

    const u64 kL2E = pk2(L2E, L2E);

    unsigned t4 = blockIdx.x * NB + tid;     // handles elements 4t..4t+3
    float4 X1 = reinterpret_cast<const float4*>(x)[2 * t4];       // elems 4t, 4t+1
    float4 X2 = reinterpret_cast<const float4*>(x)[2 * t4 + 1];   // elems 4t+2, 4t+3
    u64 xA0 = pk2(X1.x, X1.z), xA1 = pk2(X1.y, X1.w);
    u64 xB0 = pk2(X2.x, X2.z), xB1 = pk2(X2.y, X2.w);

    // fc1: 9x2 + act
    u64 hA[9], hB[9];
#pragma unroll
    for (int j = 0; j < 9; j++) {
        u64 w0 = sW1[j * 2 + 0], w1 = sW1[j * 2 + 1], bj = sb1[j];
        u64 a = ffma2(w1, xA1, ffma2(w0, xA0, bj));
        u64 b = ffma2(w1, xB1, ffma2(w0, xB0, bj));
        hA[j] = act2(a, kL2E);
        hB[j] = act2(b, kL2E);
    }

    // fc2..fc20: 19 layers of 9x9 + act (adjusted bias)
#pragma unroll 1
    for (int l = 0; l < NLAYER; l++) {
        const u64* W  = &sW[l * 90];
        const u64* bb = &sb[l * 9];
        u64 nA[9], nB[9];
#pragma unroll
        for (int j = 0; j < 9; j++) {
            u64 bj = bb[j];
            u64 a0 = bj, a1 = bj;
#pragma unroll
            for (int i = 0; i < 8; i += 2) {
                ulonglong2 w = *reinterpret_cast<const ulonglong2*>(W + j * 10 + i);
                a0 = ffma2(w.x, hA[i],     a0);
                a1 = ffma2(w.x, hB[i],     a1);
                a0 = ffma2(w.y, hA[i + 1], a0);
                a1 = ffma2(w.y, hB[i + 1], a1);
            }
            u64 w8 = W[j * 10 + 8];
            a0 = ffma2(w8, hA[8], a0);
            a1 = ffma2(w8, hB[8], a1);
            nA[j] = a0; nB[j] = a1;
        }
#pragma unroll
        for (int j = 0; j < 9; j++) {
            hA[j] = act2(nA[j], kL2E);
            hB[j] = act2(nB[j], kL2E);
        }
    }

    // fc21: 2x9 (no activation; adjusted bias)
    u64 LA0 = sb21[0], LA1 = sb21[1];
    u64 LB0 = LA0,     LB1 = LA1;
#pragma unroll
    for (int i = 0; i < 9; i++) {
        u64 w0 = sW21[i], w1 = sW21[9 + i];
        LA0 = ffma2(w0, hA[i], LA0);
        LA1 = ffma2(w1, hA[i], LA1);
        LB0 = ffma2(w0, hB[i], LB0);
        LB1 = ffma2(w1, hB[i], LB1);
    }

    float zA0a, zA0b, zA1a, zA1b, zB0a, zB0b, zB1a, zB1b;
    unpk2(LA0, zA0a, zA0b); unpk2(LA1, zA1a, zA1b);
    unpk2(LB0, zB0a, zB0b); unpk2(LB1, zB1a, zB1b);

    float o0, o1, o2, o3;
    lsm2(zA0a, zA1a, o0, o1);
    lsm2(zA0b, zA1b, o2, o3);
    reinterpret_cast<float4*>(out)[2 * t4] = make_float4(o0, o1, o2, o3);
    lsm2(zB0a, zB1a, o0, o1);
    lsm2(zB0b, zB1b, o2, o3);
    reinterpret_cast<float4*>(out)[2 * t4 + 1] = make_float4(o0, o1, o2, o3);
}

extern "C" void kernel_launch(void* const* d_in, const int* in_sizes, int n_in,
                              void* d_out, int out_size)
{
    const float* x   = (const float*)d_in[0];
    const float* W1  = (const float*)d_in[1];
    const float* b1  = (const float*)d_in[2];
    const float* Wm  = (const float*)d_in[3];
    const float* bm  = (const float*)d_in[4];
    const float* W21 = (const float*)d_in[5];
    const float* b21 = (const float*)d_in[6];
    float* out = (float*)d_out;

    int n_elems = in_sizes[0] / 2;     // B
    int n_thr   = n_elems / 4;         // 4 elements per thread
    int grid    = (n_thr + NB - 1) / NB;

    mlp_kernel<<<grid, NB>>>(x, W1, b1, Wm, bm, W21, b21, out);
}